// round 16
// baseline (speedup 1.0000x reference)
#include <cuda_runtime.h>
#include <cuda_fp16.h>
#include <math.h>
#include <stdint.h>

#define BB 4
#define NN 2048
#define DD 512
#define HH 8
#define RR (BB*NN)   // 8192 rows
#define EE 2048      // proj width

// ---------------- scratch (static device globals; no allocation) -------------
__device__ __half g_norm[(size_t)RR*DD];   // 8 MB   LN(x) fp16
__device__ __half g_proj[(size_t)RR*EE];   // 32 MB  silu(normX @ uvqk) fp16
__device__ __half g_attn[(size_t)RR*DD];   // 8 MB   attention output fp16
__device__ __half g_oin [(size_t)RR*DD];   // 8 MB   u * LN(attn) fp16
__device__ __half g_wh  [(size_t)EE*DD];   // 2 MB   uvqk^T fp16  [n][k]
__device__ __half g_woh [(size_t)DD*DD];   // 0.5 MB o_w fp16     [n][k]

__device__ __forceinline__ float silu_f(float v) { return v / (1.0f + __expf(-v)); }

// fast fp16x2 silu: 0.5*s*(1+tanh(0.5*s)) — one MUFU per two elements
__device__ __forceinline__ uint32_t silu2u(uint32_t s) {
    uint32_t p;
    asm("{\n\t.reg .b32 hs, th;\n\t"
        "mul.f16x2 hs, %1, %2;\n\t"
        "tanh.approx.f16x2 th, hs;\n\t"
        "add.f16x2 th, th, %3;\n\t"
        "mul.f16x2 %0, hs, th;\n\t}"
        : "=r"(p) : "r"(s), "r"(0x38003800u), "r"(0x3C003C00u));
    return p;
}

// mma.sync m16n8k16 row.col f16 in, fp32 accumulate (in place)
__device__ __forceinline__ void mma16(float* d, uint32_t a0, uint32_t a1,
                                      uint32_t a2, uint32_t a3,
                                      uint32_t b0, uint32_t b1) {
    asm volatile(
        "mma.sync.aligned.m16n8k16.row.col.f32.f16.f16.f32 "
        "{%0,%1,%2,%3}, {%4,%5,%6,%7}, {%8,%9}, {%0,%1,%2,%3};"
        : "+f"(d[0]), "+f"(d[1]), "+f"(d[2]), "+f"(d[3])
        : "r"(a0), "r"(a1), "r"(a2), "r"(a3), "r"(b0), "r"(b1));
}

__device__ __forceinline__ uint32_t h2u(__half2 h) { return *(uint32_t*)&h; }

__device__ __forceinline__ uint32_t smem_u32(const void* p) {
    return (uint32_t)__cvta_generic_to_shared(p);
}

__device__ __forceinline__ void ldmx4(uint32_t& r0, uint32_t& r1,
                                      uint32_t& r2, uint32_t& r3, uint32_t a) {
    asm volatile("ldmatrix.sync.aligned.m8n8.x4.shared.b16 {%0,%1,%2,%3}, [%4];"
        : "=r"(r0), "=r"(r1), "=r"(r2), "=r"(r3) : "r"(a));
}
__device__ __forceinline__ void ldmx4t(uint32_t& r0, uint32_t& r1,
                                       uint32_t& r2, uint32_t& r3, uint32_t a) {
    asm volatile("ldmatrix.sync.aligned.m8n8.x4.trans.shared.b16 {%0,%1,%2,%3}, [%4];"
        : "=r"(r0), "=r"(r1), "=r"(r2), "=r"(r3) : "r"(a));
}

__device__ __forceinline__ void cpa16(const void* dst_smem, const void* src) {
    uint32_t d = (uint32_t)__cvta_generic_to_shared(dst_smem);
    asm volatile("cp.async.cg.shared.global [%0], [%1], 16;\n" :: "r"(d), "l"(src));
}
#define CP_COMMIT() asm volatile("cp.async.commit_group;\n" ::: "memory")
#define CP_WAIT1()  asm volatile("cp.async.wait_group 1;\n" ::: "memory")
#define CP_WAIT0()  asm volatile("cp.async.wait_group 0;\n" ::: "memory")

// ---------------- weight conversion ------------------------------------------
__global__ void cvt_uvqk_kernel(const float* __restrict__ W) {
    __shared__ float tile[32][33];
    int n0 = blockIdx.x * 32, k0 = blockIdx.y * 32;
    int tx = threadIdx.x, ty = threadIdx.y;   // 32 x 8
    #pragma unroll
    for (int j = 0; j < 4; j++)
        tile[ty + j * 8][tx] = W[(size_t)(k0 + ty + j * 8) * EE + n0 + tx];
    __syncthreads();
    #pragma unroll
    for (int j = 0; j < 4; j++)
        g_wh[(size_t)(n0 + ty + j * 8) * DD + k0 + tx] =
            __float2half(tile[tx][ty + j * 8]);
}

__global__ void cvt_ow_kernel(const float* __restrict__ W) {
    int i = blockIdx.x * 256 + threadIdx.x;
    g_woh[i] = __float2half(W[i]);
}

// ---------------- LayerNorm of x -> g_norm (fp16)  ---------------------------
__global__ void ln_x_kernel(const float* __restrict__ x) {
    int row = blockIdx.x;
    int t = threadIdx.x;
    float4 v = ((const float4*)(x + (size_t)row * DD))[t];
    float s  = v.x + v.y + v.z + v.w;
    float ss = v.x*v.x + v.y*v.y + v.z*v.z + v.w*v.w;
    #pragma unroll
    for (int o = 16; o; o >>= 1) {
        s  += __shfl_xor_sync(0xffffffffu, s,  o);
        ss += __shfl_xor_sync(0xffffffffu, ss, o);
    }
    __shared__ float shs[4], shq[4];
    if ((t & 31) == 0) { shs[t >> 5] = s; shq[t >> 5] = ss; }
    __syncthreads();
    s  = shs[0] + shs[1] + shs[2] + shs[3];
    ss = shq[0] + shq[1] + shq[2] + shq[3];
    float mu  = s * (1.0f / DD);
    float var = ss * (1.0f / DD) - mu * mu;
    float rs  = rsqrtf(var + 1e-6f);
    __half2* op = (__half2*)(g_norm + (size_t)row * DD);
    op[2*t]   = __float22half2_rn(make_float2((v.x - mu) * rs, (v.y - mu) * rs));
    op[2*t+1] = __float22half2_rn(make_float2((v.z - mu) * rs, (v.w - mu) * rs));
}

// ============================================================================
// fp16 GEMM core: CTA 128x64 (m x n), 128 thr = 4 warps (2m x 2n),
// warp tile 64x32, ldmatrix fragments, cp.async 3-stage, ONE barrier/iter.
// LDA=40 halfs -> 46KB/CTA smem, 4 CTAs/SM (4 independent barrier domains).
// ============================================================================
#define LDA 40
#define GA_SZ (128*LDA)            // A stage: 128 rows
#define GB_SZ (64*LDA)             // B stage: 64 rows
#define G_STG (GA_SZ + GB_SZ)
#define G_SMEM (3 * G_STG * (int)sizeof(__half))

// GEMM1: g_proj = silu(g_norm[8192x512] @ uvqk) ; B = g_wh [2048][512]
__global__ __launch_bounds__(128) void gemm_proj_kernel() {
    extern __shared__ __half smh[];
    __half* As[3] = { smh, smh + G_STG, smh + 2*G_STG };
    __half* Bs[3] = { smh + GA_SZ, smh + G_STG + GA_SZ, smh + 2*G_STG + GA_SZ };
    int bn = blockIdx.x * 64, bm = blockIdx.y * 128;
    int tid = threadIdx.x, lane = tid & 31, wid = tid >> 5;
    int g = lane >> 2, tig = lane & 3;
    int wm = wid >> 1, wn = wid & 1;
    float acc[4][4][4] = {};

    int a_off = (wm * 64 + (lane & 15)) * LDA + ((lane >> 4) << 3);
    int b_off = (wn * 32 + (lane & 7) + ((lane >> 4) << 3)) * LDA
              + (((lane >> 3) & 1) << 3);

    auto load_stage = [&](int s, int k0) {
        #pragma unroll
        for (int t = 0; t < 4; t++) {          // A: 512 chunks
            int idx = tid + t * 128;
            int r = idx >> 2, c = idx & 3;
            cpa16(As[s] + r * LDA + c * 8, g_norm + (size_t)(bm + r) * DD + k0 + c * 8);
        }
        #pragma unroll
        for (int t = 0; t < 2; t++) {          // B: 256 chunks
            int idx = tid + t * 128;
            int r = idx >> 2, c = idx & 3;
            cpa16(Bs[s] + r * LDA + c * 8, g_wh + (size_t)(bn + r) * DD + k0 + c * 8);
        }
    };

    load_stage(0, 0);  CP_COMMIT();
    load_stage(1, 32); CP_COMMIT();
    const int NK = DD / 32;   // 16
    for (int it = 0; it < NK; it++) {
        CP_WAIT1();
        __syncthreads();
        int buf = it % 3;
        uint32_t abase = smem_u32(As[buf]) + a_off * 2;
        uint32_t bbase = smem_u32(Bs[buf]) + b_off * 2;
        #pragma unroll
        for (int ks = 0; ks < 2; ks++) {
            uint32_t af[4][4];
            #pragma unroll
            for (int mt = 0; mt < 4; mt++)
                ldmx4(af[mt][0], af[mt][1], af[mt][2], af[mt][3],
                      abase + (mt * 16 * LDA + ks * 16) * 2);
            #pragma unroll
            for (int p = 0; p < 2; p++) {
                uint32_t b0, b1, b2, b3;
                ldmx4(b0, b1, b2, b3, bbase + (p * 16 * LDA + ks * 16) * 2);
                #pragma unroll
                for (int mt = 0; mt < 4; mt++) {
                    mma16(acc[mt][2*p],   af[mt][0], af[mt][1], af[mt][2], af[mt][3], b0, b1);
                    mma16(acc[mt][2*p+1], af[mt][0], af[mt][1], af[mt][2], af[mt][3], b2, b3);
                }
            }
        }
        if (it + 2 < NK) load_stage((it + 2) % 3, (it + 2) * 32);
        CP_COMMIT();   // unconditional: uniform group accounting
    }
    #pragma unroll
    for (int mt = 0; mt < 4; mt++) {
        int m0 = bm + wm * 64 + mt * 16 + g;
        #pragma unroll
        for (int nt = 0; nt < 4; nt++) {
            int n = bn + wn * 32 + nt * 8 + 2 * tig;
            *(__half2*)(g_proj + (size_t)m0 * EE + n) =
                __float22half2_rn(make_float2(silu_f(acc[mt][nt][0]), silu_f(acc[mt][nt][1])));
            *(__half2*)(g_proj + (size_t)(m0 + 8) * EE + n) =
                __float22half2_rn(make_float2(silu_f(acc[mt][nt][2]), silu_f(acc[mt][nt][3])));
        }
    }
}

// ============================================================================
// HSTU attention (unchanged R13 shape): q-block 128, 8 warps, P in regs,
// cp.async 3-stage K/V pipeline, ONE barrier per key-tile,
// ldmatrix (+.trans for V), fast f16x2 tanh-silu on full tiles.
// ============================================================================
#define LDH 72
#define ATT_SMEM_BYTES ((128 + 6 * 64) * LDH * (int)sizeof(__half))

__global__ __launch_bounds__(256) void attn_kernel() {
    extern __shared__ __half smh[];
    __half* Qs = smh;
    __half* Ksm[3] = { Qs + 128 * LDH, Qs + (128 + 64) * LDH, Qs + (128 + 128) * LDH };
    __half* Vsm[3] = { Qs + (128 + 192) * LDH, Qs + (128 + 256) * LDH,
                       Qs + (128 + 320) * LDH };
    int qbi = (int)(gridDim.x - 1 - blockIdx.x);
    int h = blockIdx.y, b = blockIdx.z;
    int tid = threadIdx.x;
    int w = tid >> 5, lane = tid & 31, g = lane >> 2, tig = lane & 3;
    const __half* base = g_proj + (size_t)b * NN * EE;
    const __half* Qg = base + 1024 + h * 64;
    const __half* Kg = base + 1536 + h * 64;
    const __half* Vg = base + 512  + h * 64;
    int q0 = qbi * 128;
    int r0 = w * 16 + g;

    int qa_off = (w * 16 + (lane & 15)) * LDH + ((lane >> 4) << 3);
    int kb_off = ((lane & 7) + ((lane >> 4) << 3)) * LDH + (((lane >> 3) & 1) << 3);
    int vb_off = ((lane & 7) + (((lane >> 3) & 1) << 3)) * LDH + ((lane >> 4) << 3);

    #pragma unroll
    for (int t = 0; t < 4; t++) {
        int idx = tid + t * 256;
        int r = idx >> 3, c = idx & 7;
        *(int4*)(Qs + r * LDH + c * 8) =
            *(const int4*)(Qg + (size_t)(q0 + r) * EE + c * 8);
    }

    auto load_kv = [&](int s, int m0) {
        #pragma unroll
        for (int t = 0; t < 2; t++) {
            int idx = tid + t * 256;
            int r = idx >> 3, c = idx & 7;
            cpa16(Ksm[s] + r * LDH + c * 8, Kg + (size_t)(m0 + r) * EE + c * 8);
            cpa16(Vsm[s] + r * LDH + c * 8, Vg + (size_t)(m0 + r) * EE + c * 8);
        }
    };

    float oacc[8][4] = {};
    int ntile = 2 * qbi + 2;     // always >= 2
    load_kv(0, 0);  CP_COMMIT();
    load_kv(1, 64); CP_COMMIT();

    for (int mb = 0; mb < ntile; mb++) {
        int m0 = mb * 64;
        CP_WAIT1();
        __syncthreads();
        int buf = mb % 3;

        if (m0 <= q0 + w * 16 + 15) {
            uint32_t qb32 = smem_u32(Qs) + qa_off * 2;
            uint32_t kb32 = smem_u32(Ksm[buf]) + kb_off * 2;
            uint32_t vb32 = smem_u32(Vsm[buf]) + vb_off * 2;

            float sacc[8][4] = {};
            #pragma unroll
            for (int kt = 0; kt < 4; kt++) {
                uint32_t a0, a1, a2, a3;
                ldmx4(a0, a1, a2, a3, qb32 + kt * 32);
                #pragma unroll
                for (int p = 0; p < 4; p++) {
                    uint32_t b0, b1, b2, b3;
                    ldmx4(b0, b1, b2, b3, kb32 + (p * 16 * LDH + kt * 16) * 2);
                    mma16(sacc[2*p],   a0, a1, a2, a3, b0, b1);
                    mma16(sacc[2*p+1], a0, a1, a2, a3, b2, b3);
                }
            }

            uint32_t ph[8][2];
            int gr0 = q0 + r0, gr1 = gr0 + 8;
            if (m0 + 63 > q0 + w * 16) {      // diagonal tile: exact fp32 + mask
                #pragma unroll
                for (int nt = 0; nt < 8; nt++) {
                    int c0 = m0 + nt * 8 + 2 * tig, c1 = c0 + 1;
                    float p0 = c0 <= gr0 ? silu_f(sacc[nt][0]) : 0.0f;
                    float p1 = c1 <= gr0 ? silu_f(sacc[nt][1]) : 0.0f;
                    float p2 = c0 <= gr1 ? silu_f(sacc[nt][2]) : 0.0f;
                    float p3 = c1 <= gr1 ? silu_f(sacc[nt][3]) : 0.0f;
                    ph[nt][0] = h2u(__float22half2_rn(make_float2(p0, p1)));
                    ph[nt][1] = h2u(__float22half2_rn(make_float2(p2, p3)));
                }
            } else {                           // full tile: f16x2 tanh silu
                #pragma unroll
                for (int nt = 0; nt < 8; nt++) {
                    ph[nt][0] = silu2u(h2u(__float22half2_rn(
                        make_float2(sacc[nt][0], sacc[nt][1]))));
                    ph[nt][1] = silu2u(h2u(__float22half2_rn(
                        make_float2(sacc[nt][2], sacc[nt][3]))));
                }
            }

            #pragma unroll
            for (int kt = 0; kt < 4; kt++) {
                uint32_t a0 = ph[2*kt][0], a1 = ph[2*kt][1];
                uint32_t a2 = ph[2*kt+1][0], a3 = ph[2*kt+1][1];
                #pragma unroll
                for (int p = 0; p < 4; p++) {
                    uint32_t b0, b1, b2, b3;
                    ldmx4t(b0, b1, b2, b3, vb32 + (kt * 16 * LDH + p * 16) * 2);
                    mma16(oacc[2*p],   a0, a1, a2, a3, b0, b1);
                    mma16(oacc[2*p+1], a0, a1, a2, a3, b2, b3);
                }
            }
        }

        if (mb + 2 < ntile) load_kv((mb + 2) % 3, (mb + 2) * 64);
        CP_COMMIT();   // uniform accounting
    }

    const float sc = 1.0f / NN;
    size_t row0 = (size_t)b * NN + q0 + r0;
    #pragma unroll
    for (int nt = 0; nt < 8; nt++) {
        int n = h * 64 + nt * 8 + 2 * tig;
        *(__half2*)(g_attn + row0 * DD + n) =
            __float22half2_rn(make_float2(oacc[nt][0] * sc, oacc[nt][1] * sc));
        *(__half2*)(g_attn + (row0 + 8) * DD + n) =
            __float22half2_rn(make_float2(oacc[nt][2] * sc, oacc[nt][3] * sc));
    }
}

// ---------------- LN(attn fp16) * u -> g_oin (fp16) --------------------------
__global__ void ln_attn_kernel() {
    int row = blockIdx.x;
    int t = threadIdx.x;
    const __half2* ap = (const __half2*)(g_attn + (size_t)row * DD);
    float2 a0 = __half22float2(ap[2*t]);
    float2 a1 = __half22float2(ap[2*t+1]);
    float s  = a0.x + a0.y + a1.x + a1.y;
    float ss = a0.x*a0.x + a0.y*a0.y + a1.x*a1.x + a1.y*a1.y;
    #pragma unroll
    for (int o = 16; o; o >>= 1) {
        s  += __shfl_xor_sync(0xffffffffu, s,  o);
        ss += __shfl_xor_sync(0xffffffffu, ss, o);
    }
    __shared__ float shs[4], shq[4];
    if ((t & 31) == 0) { shs[t >> 5] = s; shq[t >> 5] = ss; }
    __syncthreads();
    s  = shs[0] + shs[1] + shs[2] + shs[3];
    ss = shq[0] + shq[1] + shq[2] + shq[3];
    float mu  = s * (1.0f / DD);
    float var = ss * (1.0f / DD) - mu * mu;
    float rs  = rsqrtf(var + 1e-6f);
    const __half2* up = (const __half2*)(g_proj + (size_t)row * EE);
    float2 u0 = __half22float2(up[2*t]);
    float2 u1 = __half22float2(up[2*t+1]);
    __half2* op = (__half2*)(g_oin + (size_t)row * DD);
    op[2*t]   = __float22half2_rn(make_float2((a0.x - mu) * rs * u0.x,
                                              (a0.y - mu) * rs * u0.y));
    op[2*t+1] = __float22half2_rn(make_float2((a1.x - mu) * rs * u1.x,
                                              (a1.y - mu) * rs * u1.y));
}

// ============================================================================
// GEMM2: out = g_oin[8192x512] @ o_w^T + o_b + x  (fp32 out) — 128x64 CTA
// ============================================================================
__global__ __launch_bounds__(128) void gemm_out_kernel(
    const float* __restrict__ bias, const float* __restrict__ x,
    float* __restrict__ out) {
    extern __shared__ __half smh[];
    __half* As[3] = { smh, smh + G_STG, smh + 2*G_STG };
    __half* Bs[3] = { smh + GA_SZ, smh + G_STG + GA_SZ, smh + 2*G_STG + GA_SZ };
    int bn = blockIdx.x * 64, bm = blockIdx.y * 128;
    int tid = threadIdx.x, lane = tid & 31, wid = tid >> 5;
    int g = lane >> 2, tig = lane & 3;
    int wm = wid >> 1, wn = wid & 1;
    float acc[4][4][4] = {};

    int a_off = (wm * 64 + (lane & 15)) * LDA + ((lane >> 4) << 3);
    int b_off = (wn * 32 + (lane & 7) + ((lane >> 4) << 3)) * LDA
              + (((lane >> 3) & 1) << 3);

    auto load_stage = [&](int s, int k0) {
        #pragma unroll
        for (int t = 0; t < 4; t++) {
            int idx = tid + t * 128;
            int r = idx >> 2, c = idx & 3;
            cpa16(As[s] + r * LDA + c * 8, g_oin + (size_t)(bm + r) * DD + k0 + c * 8);
        }
        #pragma unroll
        for (int t = 0; t < 2; t++) {
            int idx = tid + t * 128;
            int r = idx >> 2, c = idx & 3;
            cpa16(Bs[s] + r * LDA + c * 8, g_woh + (size_t)(bn + r) * DD + k0 + c * 8);
        }
    };

    load_stage(0, 0);  CP_COMMIT();
    load_stage(1, 32); CP_COMMIT();
    const int NK = DD / 32;
    for (int it = 0; it < NK; it++) {
        CP_WAIT1();
        __syncthreads();
        int buf = it % 3;
        uint32_t abase = smem_u32(As[buf]) + a_off * 2;
        uint32_t bbase = smem_u32(Bs[buf]) + b_off * 2;
        #pragma unroll
        for (int ks = 0; ks < 2; ks++) {
            uint32_t af[4][4];
            #pragma unroll
            for (int mt = 0; mt < 4; mt++)
                ldmx4(af[mt][0], af[mt][1], af[mt][2], af[mt][3],
                      abase + (mt * 16 * LDA + ks * 16) * 2);
            #pragma unroll
            for (int p = 0; p < 2; p++) {
                uint32_t b0, b1, b2, b3;
                ldmx4(b0, b1, b2, b3, bbase + (p * 16 * LDA + ks * 16) * 2);
                #pragma unroll
                for (int mt = 0; mt < 4; mt++) {
                    mma16(acc[mt][2*p],   af[mt][0], af[mt][1], af[mt][2], af[mt][3], b0, b1);
                    mma16(acc[mt][2*p+1], af[mt][0], af[mt][1], af[mt][2], af[mt][3], b2, b3);
                }
            }
        }
        if (it + 2 < NK) load_stage((it + 2) % 3, (it + 2) * 32);
        CP_COMMIT();
    }
    #pragma unroll
    for (int mt = 0; mt < 4; mt++) {
        size_t m0 = (size_t)(bm + wm * 64 + mt * 16 + g);
        #pragma unroll
        for (int nt = 0; nt < 4; nt++) {
            int n = bn + wn * 32 + nt * 8 + 2 * tig;
            float2 b2 = *(const float2*)(bias + n);
            float2 x0 = *(const float2*)(x + m0 * DD + n);
            float2 x1 = *(const float2*)(x + (m0 + 8) * DD + n);
            *(float2*)(out + m0 * DD + n) =
                make_float2(acc[mt][nt][0] + b2.x + x0.x,
                            acc[mt][nt][1] + b2.y + x0.y);
            *(float2*)(out + (m0 + 8) * DD + n) =
                make_float2(acc[mt][nt][2] + b2.x + x1.x,
                            acc[mt][nt][3] + b2.y + x1.y);
        }
    }
}

// ---------------- launch -----------------------------------------------------
extern "C" void kernel_launch(void* const* d_in, const int* in_sizes, int n_in,
                              void* d_out, int out_size) {
    const float* x    = (const float*)d_in[0];
    // d_in[1] = invalid_attn_mask (tril causal) -- implemented analytically
    const float* uvqk = (const float*)d_in[2];
    const float* o_w  = (const float*)d_in[3];
    const float* o_b  = (const float*)d_in[4];
    float* out = (float*)d_out;

    ln_x_kernel<<<RR, 128>>>(x);

    dim3 gw(EE / 32, DD / 32);
    cvt_uvqk_kernel<<<gw, dim3(32, 8)>>>(uvqk);
    cvt_ow_kernel<<<(DD * DD) / 256, 256>>>(o_w);

    cudaFuncSetAttribute(gemm_proj_kernel,
                         cudaFuncAttributeMaxDynamicSharedMemorySize, G_SMEM);
    dim3 g1(EE / 64, RR / 128);
    gemm_proj_kernel<<<g1, 128, G_SMEM>>>();

    cudaFuncSetAttribute(attn_kernel,
                         cudaFuncAttributeMaxDynamicSharedMemorySize,
                         ATT_SMEM_BYTES);
    dim3 ga(NN / 128, HH, BB);
    attn_kernel<<<ga, 256, ATT_SMEM_BYTES>>>();

    ln_attn_kernel<<<RR, 128>>>();

    cudaFuncSetAttribute(gemm_out_kernel,
                         cudaFuncAttributeMaxDynamicSharedMemorySize, G_SMEM);
    dim3 g2(DD / 64, RR / 128);
    gemm_out_kernel<<<g2, 128, G_SMEM>>>(o_b, x, out);
}

// round 17
// speedup vs baseline: 1.1175x; 1.1175x over previous
#include <cuda_runtime.h>
#include <cuda_fp16.h>
#include <math.h>
#include <stdint.h>

#define BB 4
#define NN 2048
#define DD 512
#define HH 8
#define RR (BB*NN)   // 8192 rows
#define EE 2048      // proj width

// ---------------- scratch (static device globals; no allocation) -------------
__device__ __half g_norm[(size_t)RR*DD];   // 8 MB   LN(x) fp16
__device__ __half g_proj[(size_t)RR*EE];   // 32 MB  silu(normX @ uvqk) fp16
__device__ __half g_attn[(size_t)RR*DD];   // 8 MB   attention output fp16
__device__ __half g_oin [(size_t)RR*DD];   // 8 MB   u * LN(attn) fp16
__device__ __half g_wh  [(size_t)EE*DD];   // 2 MB   uvqk^T fp16  [n][k]
__device__ __half g_woh [(size_t)DD*DD];   // 0.5 MB o_w fp16     [n][k]

__device__ __forceinline__ float silu_f(float v) { return v / (1.0f + __expf(-v)); }

// fast fp16x2 silu: 0.5*s*(1+tanh(0.5*s)) — one MUFU per two elements
__device__ __forceinline__ uint32_t silu2u(uint32_t s) {
    uint32_t p;
    asm("{\n\t.reg .b32 hs, th;\n\t"
        "mul.f16x2 hs, %1, %2;\n\t"
        "tanh.approx.f16x2 th, hs;\n\t"
        "add.f16x2 th, th, %3;\n\t"
        "mul.f16x2 %0, hs, th;\n\t}"
        : "=r"(p) : "r"(s), "r"(0x38003800u), "r"(0x3C003C00u));
    return p;
}

// mma.sync m16n8k16 row.col f16 in, fp32 accumulate (in place)
__device__ __forceinline__ void mma16(float* d, uint32_t a0, uint32_t a1,
                                      uint32_t a2, uint32_t a3,
                                      uint32_t b0, uint32_t b1) {
    asm volatile(
        "mma.sync.aligned.m16n8k16.row.col.f32.f16.f16.f32 "
        "{%0,%1,%2,%3}, {%4,%5,%6,%7}, {%8,%9}, {%0,%1,%2,%3};"
        : "+f"(d[0]), "+f"(d[1]), "+f"(d[2]), "+f"(d[3])
        : "r"(a0), "r"(a1), "r"(a2), "r"(a3), "r"(b0), "r"(b1));
}

__device__ __forceinline__ uint32_t h2u(__half2 h) { return *(uint32_t*)&h; }

__device__ __forceinline__ uint32_t smem_u32(const void* p) {
    return (uint32_t)__cvta_generic_to_shared(p);
}

__device__ __forceinline__ void ldmx4(uint32_t& r0, uint32_t& r1,
                                      uint32_t& r2, uint32_t& r3, uint32_t a) {
    asm volatile("ldmatrix.sync.aligned.m8n8.x4.shared.b16 {%0,%1,%2,%3}, [%4];"
        : "=r"(r0), "=r"(r1), "=r"(r2), "=r"(r3) : "r"(a));
}
__device__ __forceinline__ void ldmx4t(uint32_t& r0, uint32_t& r1,
                                       uint32_t& r2, uint32_t& r3, uint32_t a) {
    asm volatile("ldmatrix.sync.aligned.m8n8.x4.trans.shared.b16 {%0,%1,%2,%3}, [%4];"
        : "=r"(r0), "=r"(r1), "=r"(r2), "=r"(r3) : "r"(a));
}

__device__ __forceinline__ void cpa16(const void* dst_smem, const void* src) {
    uint32_t d = (uint32_t)__cvta_generic_to_shared(dst_smem);
    asm volatile("cp.async.cg.shared.global [%0], [%1], 16;\n" :: "r"(d), "l"(src));
}
#define CP_COMMIT() asm volatile("cp.async.commit_group;\n" ::: "memory")
#define CP_WAIT2()  asm volatile("cp.async.wait_group 2;\n" ::: "memory")
#define CP_WAIT1()  asm volatile("cp.async.wait_group 1;\n" ::: "memory")
#define CP_WAIT0()  asm volatile("cp.async.wait_group 0;\n" ::: "memory")

// ---------------- weight conversion ------------------------------------------
__global__ void cvt_uvqk_kernel(const float* __restrict__ W) {
    __shared__ float tile[32][33];
    int n0 = blockIdx.x * 32, k0 = blockIdx.y * 32;
    int tx = threadIdx.x, ty = threadIdx.y;   // 32 x 8
    #pragma unroll
    for (int j = 0; j < 4; j++)
        tile[ty + j * 8][tx] = W[(size_t)(k0 + ty + j * 8) * EE + n0 + tx];
    __syncthreads();
    #pragma unroll
    for (int j = 0; j < 4; j++)
        g_wh[(size_t)(n0 + ty + j * 8) * DD + k0 + tx] =
            __float2half(tile[tx][ty + j * 8]);
}

__global__ void cvt_ow_kernel(const float* __restrict__ W) {
    int i = blockIdx.x * 256 + threadIdx.x;
    g_woh[i] = __float2half(W[i]);
}

// ---------------- LayerNorm of x -> g_norm (fp16)  ---------------------------
__global__ void ln_x_kernel(const float* __restrict__ x) {
    int row = blockIdx.x;
    int t = threadIdx.x;
    float4 v = ((const float4*)(x + (size_t)row * DD))[t];
    float s  = v.x + v.y + v.z + v.w;
    float ss = v.x*v.x + v.y*v.y + v.z*v.z + v.w*v.w;
    #pragma unroll
    for (int o = 16; o; o >>= 1) {
        s  += __shfl_xor_sync(0xffffffffu, s,  o);
        ss += __shfl_xor_sync(0xffffffffu, ss, o);
    }
    __shared__ float shs[4], shq[4];
    if ((t & 31) == 0) { shs[t >> 5] = s; shq[t >> 5] = ss; }
    __syncthreads();
    s  = shs[0] + shs[1] + shs[2] + shs[3];
    ss = shq[0] + shq[1] + shq[2] + shq[3];
    float mu  = s * (1.0f / DD);
    float var = ss * (1.0f / DD) - mu * mu;
    float rs  = rsqrtf(var + 1e-6f);
    __half2* op = (__half2*)(g_norm + (size_t)row * DD);
    op[2*t]   = __float22half2_rn(make_float2((v.x - mu) * rs, (v.y - mu) * rs));
    op[2*t+1] = __float22half2_rn(make_float2((v.z - mu) * rs, (v.w - mu) * rs));
}

// ============================================================================
// fp16 GEMM core (R13-best shape): CTA 128x128xk32, 8 warps (2m x 4n),
// warp tile 64x32, ldmatrix fragments, cp.async 4-stage, ONE barrier/iter.
// LDA=40 halfs -> 80KB/CTA smem, 2 CTAs/SM.
// ============================================================================
#define LDA 40
#define G_ASZ (128*LDA)
#define G_SMEM (8 * G_ASZ * (int)sizeof(__half))   // 4 stages x (A+B)

// GEMM1: g_proj = silu(g_norm[8192x512] @ uvqk) ; B = g_wh [2048][512]
__global__ __launch_bounds__(256) void gemm_proj_kernel() {
    extern __shared__ __half smh[];
    __half* As[4] = { smh, smh + G_ASZ, smh + 2*G_ASZ, smh + 3*G_ASZ };
    __half* Bs[4] = { smh + 4*G_ASZ, smh + 5*G_ASZ, smh + 6*G_ASZ, smh + 7*G_ASZ };
    int bn = blockIdx.x * 128, bm = blockIdx.y * 128;
    int tid = threadIdx.x, lane = tid & 31, wid = tid >> 5;
    int g = lane >> 2, tig = lane & 3;
    int wm = wid >> 2, wn = wid & 3;
    float acc[4][4][4] = {};

    int a_off = (wm * 64 + (lane & 15)) * LDA + ((lane >> 4) << 3);
    int b_off = (wn * 32 + (lane & 7) + ((lane >> 4) << 3)) * LDA
              + (((lane >> 3) & 1) << 3);

    auto load_stage = [&](int s, int k0) {
        #pragma unroll
        for (int t = 0; t < 2; t++) {
            int idx = tid + t * 256;
            int r = idx >> 2, c = idx & 3;
            cpa16(As[s] + r * LDA + c * 8, g_norm + (size_t)(bm + r) * DD + k0 + c * 8);
            cpa16(Bs[s] + r * LDA + c * 8, g_wh   + (size_t)(bn + r) * DD + k0 + c * 8);
        }
    };

    #pragma unroll
    for (int s = 0; s < 3; s++) { load_stage(s, s * 32); CP_COMMIT(); }
    const int NK = DD / 32;   // 16
    for (int it = 0; it < NK; it++) {
        CP_WAIT2();
        __syncthreads();
        uint32_t abase = smem_u32(As[it & 3]) + a_off * 2;
        uint32_t bbase = smem_u32(Bs[it & 3]) + b_off * 2;
        #pragma unroll
        for (int ks = 0; ks < 2; ks++) {
            uint32_t af[4][4];
            #pragma unroll
            for (int mt = 0; mt < 4; mt++)
                ldmx4(af[mt][0], af[mt][1], af[mt][2], af[mt][3],
                      abase + (mt * 16 * LDA + ks * 16) * 2);
            #pragma unroll
            for (int p = 0; p < 2; p++) {
                uint32_t b0, b1, b2, b3;
                ldmx4(b0, b1, b2, b3, bbase + (p * 16 * LDA + ks * 16) * 2);
                #pragma unroll
                for (int mt = 0; mt < 4; mt++) {
                    mma16(acc[mt][2*p],   af[mt][0], af[mt][1], af[mt][2], af[mt][3], b0, b1);
                    mma16(acc[mt][2*p+1], af[mt][0], af[mt][1], af[mt][2], af[mt][3], b2, b3);
                }
            }
        }
        if (it + 3 < NK) load_stage((it + 3) & 3, (it + 3) * 32);
        CP_COMMIT();   // unconditional: uniform group accounting
    }
    #pragma unroll
    for (int mt = 0; mt < 4; mt++) {
        int m0 = bm + wm * 64 + mt * 16 + g;
        #pragma unroll
        for (int nt = 0; nt < 4; nt++) {
            int n = bn + wn * 32 + nt * 8 + 2 * tig;
            *(__half2*)(g_proj + (size_t)m0 * EE + n) =
                __float22half2_rn(make_float2(silu_f(acc[mt][nt][0]), silu_f(acc[mt][nt][1])));
            *(__half2*)(g_proj + (size_t)(m0 + 8) * EE + n) =
                __float22half2_rn(make_float2(silu_f(acc[mt][nt][2]), silu_f(acc[mt][nt][3])));
        }
    }
}

// ============================================================================
// HSTU attention: q-block 128, 8 warps, P register-resident,
// cp.async 4-stage K/V pipeline (WAIT2 -> 2 tiles in flight),
// ONE barrier per key-tile, ldmatrix (+.trans for V), f16x2 tanh-silu.
// smem = (128 + 8*64) rows * 72 halfs = 92.2KB -> 2 CTAs/SM.
// ============================================================================
#define LDH 72
#define ATT_SMEM_BYTES ((128 + 8 * 64) * LDH * (int)sizeof(__half))

__global__ __launch_bounds__(256) void attn_kernel() {
    extern __shared__ __half smh[];
    __half* Qs = smh;
    __half* Ksm[4] = { Qs + 128 * LDH, Qs + (128 + 64) * LDH,
                       Qs + (128 + 128) * LDH, Qs + (128 + 192) * LDH };
    __half* Vsm[4] = { Qs + (128 + 256) * LDH, Qs + (128 + 320) * LDH,
                       Qs + (128 + 384) * LDH, Qs + (128 + 448) * LDH };
    int qbi = (int)(gridDim.x - 1 - blockIdx.x);
    int h = blockIdx.y, b = blockIdx.z;
    int tid = threadIdx.x;
    int w = tid >> 5, lane = tid & 31, g = lane >> 2, tig = lane & 3;
    const __half* base = g_proj + (size_t)b * NN * EE;
    const __half* Qg = base + 1024 + h * 64;
    const __half* Kg = base + 1536 + h * 64;
    const __half* Vg = base + 512  + h * 64;
    int q0 = qbi * 128;
    int r0 = w * 16 + g;

    int qa_off = (w * 16 + (lane & 15)) * LDH + ((lane >> 4) << 3);
    int kb_off = ((lane & 7) + ((lane >> 4) << 3)) * LDH + (((lane >> 3) & 1) << 3);
    int vb_off = ((lane & 7) + (((lane >> 3) & 1) << 3)) * LDH + ((lane >> 4) << 3);

    #pragma unroll
    for (int t = 0; t < 4; t++) {
        int idx = tid + t * 256;
        int r = idx >> 3, c = idx & 7;
        *(int4*)(Qs + r * LDH + c * 8) =
            *(const int4*)(Qg + (size_t)(q0 + r) * EE + c * 8);
    }

    auto load_kv = [&](int s, int m0) {
        #pragma unroll
        for (int t = 0; t < 2; t++) {
            int idx = tid + t * 256;
            int r = idx >> 3, c = idx & 7;
            cpa16(Ksm[s] + r * LDH + c * 8, Kg + (size_t)(m0 + r) * EE + c * 8);
            cpa16(Vsm[s] + r * LDH + c * 8, Vg + (size_t)(m0 + r) * EE + c * 8);
        }
    };

    float oacc[8][4] = {};
    int ntile = 2 * qbi + 2;     // always >= 2
    // preload 3 tiles; indices 0..2 always in-bounds (rows <= 191 < NN)
    load_kv(0, 0);   CP_COMMIT();
    load_kv(1, 64);  CP_COMMIT();
    load_kv(2, 128); CP_COMMIT();

    for (int mb = 0; mb < ntile; mb++) {
        int m0 = mb * 64;
        CP_WAIT2();
        __syncthreads();
        int buf = mb & 3;

        if (m0 <= q0 + w * 16 + 15) {
            uint32_t qb32 = smem_u32(Qs) + qa_off * 2;
            uint32_t kb32 = smem_u32(Ksm[buf]) + kb_off * 2;
            uint32_t vb32 = smem_u32(Vsm[buf]) + vb_off * 2;

            float sacc[8][4] = {};
            #pragma unroll
            for (int kt = 0; kt < 4; kt++) {
                uint32_t a0, a1, a2, a3;
                ldmx4(a0, a1, a2, a3, qb32 + kt * 32);
                #pragma unroll
                for (int p = 0; p < 4; p++) {
                    uint32_t b0, b1, b2, b3;
                    ldmx4(b0, b1, b2, b3, kb32 + (p * 16 * LDH + kt * 16) * 2);
                    mma16(sacc[2*p],   a0, a1, a2, a3, b0, b1);
                    mma16(sacc[2*p+1], a0, a1, a2, a3, b2, b3);
                }
            }

            uint32_t ph[8][2];
            int gr0 = q0 + r0, gr1 = gr0 + 8;
            if (m0 + 63 > q0 + w * 16) {      // diagonal tile: exact fp32 + mask
                #pragma unroll
                for (int nt = 0; nt < 8; nt++) {
                    int c0 = m0 + nt * 8 + 2 * tig, c1 = c0 + 1;
                    float p0 = c0 <= gr0 ? silu_f(sacc[nt][0]) : 0.0f;
                    float p1 = c1 <= gr0 ? silu_f(sacc[nt][1]) : 0.0f;
                    float p2 = c0 <= gr1 ? silu_f(sacc[nt][2]) : 0.0f;
                    float p3 = c1 <= gr1 ? silu_f(sacc[nt][3]) : 0.0f;
                    ph[nt][0] = h2u(__float22half2_rn(make_float2(p0, p1)));
                    ph[nt][1] = h2u(__float22half2_rn(make_float2(p2, p3)));
                }
            } else {                           // full tile: f16x2 tanh silu
                #pragma unroll
                for (int nt = 0; nt < 8; nt++) {
                    ph[nt][0] = silu2u(h2u(__float22half2_rn(
                        make_float2(sacc[nt][0], sacc[nt][1]))));
                    ph[nt][1] = silu2u(h2u(__float22half2_rn(
                        make_float2(sacc[nt][2], sacc[nt][3]))));
                }
            }

            #pragma unroll
            for (int kt = 0; kt < 4; kt++) {
                uint32_t a0 = ph[2*kt][0], a1 = ph[2*kt][1];
                uint32_t a2 = ph[2*kt+1][0], a3 = ph[2*kt+1][1];
                #pragma unroll
                for (int p = 0; p < 4; p++) {
                    uint32_t b0, b1, b2, b3;
                    ldmx4t(b0, b1, b2, b3, vb32 + (kt * 16 * LDH + p * 16) * 2);
                    mma16(oacc[2*p],   a0, a1, a2, a3, b0, b1);
                    mma16(oacc[2*p+1], a0, a1, a2, a3, b2, b3);
                }
            }
        }

        if (mb + 3 < ntile) load_kv((mb + 3) & 3, (mb + 3) * 64);
        CP_COMMIT();   // uniform accounting
    }

    const float sc = 1.0f / NN;
    size_t row0 = (size_t)b * NN + q0 + r0;
    #pragma unroll
    for (int nt = 0; nt < 8; nt++) {
        int n = h * 64 + nt * 8 + 2 * tig;
        *(__half2*)(g_attn + row0 * DD + n) =
            __float22half2_rn(make_float2(oacc[nt][0] * sc, oacc[nt][1] * sc));
        *(__half2*)(g_attn + (row0 + 8) * DD + n) =
            __float22half2_rn(make_float2(oacc[nt][2] * sc, oacc[nt][3] * sc));
    }
}

// ---------------- LN(attn fp16) * u -> g_oin (fp16) --------------------------
__global__ void ln_attn_kernel() {
    int row = blockIdx.x;
    int t = threadIdx.x;
    const __half2* ap = (const __half2*)(g_attn + (size_t)row * DD);
    float2 a0 = __half22float2(ap[2*t]);
    float2 a1 = __half22float2(ap[2*t+1]);
    float s  = a0.x + a0.y + a1.x + a1.y;
    float ss = a0.x*a0.x + a0.y*a0.y + a1.x*a1.x + a1.y*a1.y;
    #pragma unroll
    for (int o = 16; o; o >>= 1) {
        s  += __shfl_xor_sync(0xffffffffu, s,  o);
        ss += __shfl_xor_sync(0xffffffffu, ss, o);
    }
    __shared__ float shs[4], shq[4];
    if ((t & 31) == 0) { shs[t >> 5] = s; shq[t >> 5] = ss; }
    __syncthreads();
    s  = shs[0] + shs[1] + shs[2] + shs[3];
    ss = shq[0] + shq[1] + shq[2] + shq[3];
    float mu  = s * (1.0f / DD);
    float var = ss * (1.0f / DD) - mu * mu;
    float rs  = rsqrtf(var + 1e-6f);
    const __half2* up = (const __half2*)(g_proj + (size_t)row * EE);
    float2 u0 = __half22float2(up[2*t]);
    float2 u1 = __half22float2(up[2*t+1]);
    __half2* op = (__half2*)(g_oin + (size_t)row * DD);
    op[2*t]   = __float22half2_rn(make_float2((a0.x - mu) * rs * u0.x,
                                              (a0.y - mu) * rs * u0.y));
    op[2*t+1] = __float22half2_rn(make_float2((a1.x - mu) * rs * u1.x,
                                              (a1.y - mu) * rs * u1.y));
}

// ============================================================================
// GEMM2: out = g_oin[8192x512] @ o_w^T + o_b + x  (fp32 out)  — R13 shape
// ============================================================================
__global__ __launch_bounds__(256) void gemm_out_kernel(
    const float* __restrict__ bias, const float* __restrict__ x,
    float* __restrict__ out) {
    extern __shared__ __half smh[];
    __half* As[4] = { smh, smh + G_ASZ, smh + 2*G_ASZ, smh + 3*G_ASZ };
    __half* Bs[4] = { smh + 4*G_ASZ, smh + 5*G_ASZ, smh + 6*G_ASZ, smh + 7*G_ASZ };
    int bn = blockIdx.x * 128, bm = blockIdx.y * 128;
    int tid = threadIdx.x, lane = tid & 31, wid = tid >> 5;
    int g = lane >> 2, tig = lane & 3;
    int wm = wid >> 2, wn = wid & 3;
    float acc[4][4][4] = {};

    int a_off = (wm * 64 + (lane & 15)) * LDA + ((lane >> 4) << 3);
    int b_off = (wn * 32 + (lane & 7) + ((lane >> 4) << 3)) * LDA
              + (((lane >> 3) & 1) << 3);

    auto load_stage = [&](int s, int k0) {
        #pragma unroll
        for (int t = 0; t < 2; t++) {
            int idx = tid + t * 256;
            int r = idx >> 2, c = idx & 3;
            cpa16(As[s] + r * LDA + c * 8, g_oin + (size_t)(bm + r) * DD + k0 + c * 8);
            cpa16(Bs[s] + r * LDA + c * 8, g_woh + (size_t)(bn + r) * DD + k0 + c * 8);
        }
    };

    #pragma unroll
    for (int s = 0; s < 3; s++) { load_stage(s, s * 32); CP_COMMIT(); }
    const int NK = DD / 32;
    for (int it = 0; it < NK; it++) {
        CP_WAIT2();
        __syncthreads();
        uint32_t abase = smem_u32(As[it & 3]) + a_off * 2;
        uint32_t bbase = smem_u32(Bs[it & 3]) + b_off * 2;
        #pragma unroll
        for (int ks = 0; ks < 2; ks++) {
            uint32_t af[4][4];
            #pragma unroll
            for (int mt = 0; mt < 4; mt++)
                ldmx4(af[mt][0], af[mt][1], af[mt][2], af[mt][3],
                      abase + (mt * 16 * LDA + ks * 16) * 2);
            #pragma unroll
            for (int p = 0; p < 2; p++) {
                uint32_t b0, b1, b2, b3;
                ldmx4(b0, b1, b2, b3, bbase + (p * 16 * LDA + ks * 16) * 2);
                #pragma unroll
                for (int mt = 0; mt < 4; mt++) {
                    mma16(acc[mt][2*p],   af[mt][0], af[mt][1], af[mt][2], af[mt][3], b0, b1);
                    mma16(acc[mt][2*p+1], af[mt][0], af[mt][1], af[mt][2], af[mt][3], b2, b3);
                }
            }
        }
        if (it + 3 < NK) load_stage((it + 3) & 3, (it + 3) * 32);
        CP_COMMIT();
    }
    #pragma unroll
    for (int mt = 0; mt < 4; mt++) {
        size_t m0 = (size_t)(bm + wm * 64 + mt * 16 + g);
        #pragma unroll
        for (int nt = 0; nt < 4; nt++) {
            int n = bn + wn * 32 + nt * 8 + 2 * tig;
            float2 b2 = *(const float2*)(bias + n);
            float2 x0 = *(const float2*)(x + m0 * DD + n);
            float2 x1 = *(const float2*)(x + (m0 + 8) * DD + n);
            *(float2*)(out + m0 * DD + n) =
                make_float2(acc[mt][nt][0] + b2.x + x0.x,
                            acc[mt][nt][1] + b2.y + x0.y);
            *(float2*)(out + (m0 + 8) * DD + n) =
                make_float2(acc[mt][nt][2] + b2.x + x1.x,
                            acc[mt][nt][3] + b2.y + x1.y);
        }
    }
}

// ---------------- launch -----------------------------------------------------
extern "C" void kernel_launch(void* const* d_in, const int* in_sizes, int n_in,
                              void* d_out, int out_size) {
    const float* x    = (const float*)d_in[0];
    // d_in[1] = invalid_attn_mask (tril causal) -- implemented analytically
    const float* uvqk = (const float*)d_in[2];
    const float* o_w  = (const float*)d_in[3];
    const float* o_b  = (const float*)d_in[4];
    float* out = (float*)d_out;

    ln_x_kernel<<<RR, 128>>>(x);

    dim3 gw(EE / 32, DD / 32);
    cvt_uvqk_kernel<<<gw, dim3(32, 8)>>>(uvqk);
    cvt_ow_kernel<<<(DD * DD) / 256, 256>>>(o_w);

    cudaFuncSetAttribute(gemm_proj_kernel,
                         cudaFuncAttributeMaxDynamicSharedMemorySize, G_SMEM);
    dim3 g1(EE / 128, RR / 128);
    gemm_proj_kernel<<<g1, 256, G_SMEM>>>();

    cudaFuncSetAttribute(attn_kernel,
                         cudaFuncAttributeMaxDynamicSharedMemorySize,
                         ATT_SMEM_BYTES);
    dim3 ga(NN / 128, HH, BB);
    attn_kernel<<<ga, 256, ATT_SMEM_BYTES>>>();

    ln_attn_kernel<<<RR, 128>>>();

    cudaFuncSetAttribute(gemm_out_kernel,
                         cudaFuncAttributeMaxDynamicSharedMemorySize, G_SMEM);
    dim3 g2(DD / 128, RR / 128);
    gemm_out_kernel<<<g2, 256, G_SMEM>>>(o_b, x, out);
}